// round 3
// baseline (speedup 1.0000x reference)
#include <cuda_runtime.h>
#include <math.h>

// ---------------------------------------------------------------------------
// YoloLoss: fused single-pass reduction over N*S*S = 802816 cells.
// Inputs (metadata order): pred_tensor [N,S,S,30] f32, target_boxes [N,S,S,4]
// f32, target_cls [N,S,S,20] f32, has_object_map [N,S,S] (bool -> dtype
// detected at runtime). Output: 5 f32 (total, reg, conf, noobj, cls).
// ---------------------------------------------------------------------------

#define S_INV (1.0f / 14.0f)

// acc[0]=n_obj, acc[1]=cls_sum, acc[2]=noobj_sum, acc[3]=reg_sum, acc[4]=conf_sum
__device__ double g_acc[5];
__device__ int g_flag_gt1;   // set if any byte in objmap > 1  -> float32 storage
__device__ int g_flag_off4;  // set if nonzero byte at idx%4!=0 -> uint8 storage

__global__ void init_kernel() {
    if (threadIdx.x < 5) g_acc[threadIdx.x] = 0.0;
    if (threadIdx.x == 0) { g_flag_gt1 = 0; g_flag_off4 = 0; }
}

// Detect storage dtype of has_object_map by byte pattern. Reads exactly n
// bytes, which is a safe lower bound for all candidate layouts (uint8: n
// bytes, int32: 4n, float32: 4n).
//   float32 0.0/1.0 -> bytes {0,0,0x80,0x3F} -> gt1 fires
//   int32   0/1     -> nonzero bytes only at idx%4==0 -> neither fires
//   uint8   0/1     -> nonzero bytes at arbitrary idx -> off4 fires
__global__ void detect_kernel(const unsigned char* __restrict__ p, int n) {
    __shared__ int s1, s2;
    if (threadIdx.x == 0) { s1 = 0; s2 = 0; }
    __syncthreads();
    int l1 = 0, l2 = 0;
    for (int i = blockIdx.x * blockDim.x + threadIdx.x; i < n;
         i += gridDim.x * blockDim.x) {
        unsigned char b = p[i];
        l1 |= (b > 1);
        l2 |= ((b != 0) & ((i & 3) != 0));
    }
    if (l1) atomicOr(&s1, 1);
    if (l2) atomicOr(&s2, 1);
    __syncthreads();
    if (threadIdx.x == 0) {
        if (s1) atomicOr(&g_flag_gt1, 1);
        if (s2) atomicOr(&g_flag_off4, 1);
    }
}

__device__ __forceinline__ float iou_xyxy(
    float x1, float y1, float x2, float y2,
    float tx1, float ty1, float tx2, float ty2)
{
    float lx = fmaxf(x1, tx1), ly = fmaxf(y1, ty1);
    float rx = fminf(x2, tx2), ry = fminf(y2, ty2);
    float w = fmaxf(rx - lx, 0.0f), h = fmaxf(ry - ly, 0.0f);
    float inter = w * h;
    float a1 = (x2 - x1) * (y2 - y1);
    float a2 = (tx2 - tx1) * (ty2 - ty1);
    return inter / (a1 + a2 - inter);
}

__global__ void __launch_bounds__(256)
yolo_kernel(const float* __restrict__ pred,
            const float* __restrict__ tbox,
            const float* __restrict__ tcls,
            const void*  __restrict__ objp,
            int ncells)
{
    int i = blockIdx.x * blockDim.x + threadIdx.x;

    float v_nobj = 0.0f, v_cls = 0.0f, v_noobj = 0.0f, v_reg = 0.0f, v_conf = 0.0f;

    if (i < ncells) {
        // uniform (all threads take the same path) dtype dispatch
        float obj;
        if (g_flag_gt1) {
            obj = ((const float*)objp)[i];
        } else if (g_flag_off4) {
            obj = (float)((const unsigned char*)objp)[i];
        } else {
            obj = (float)((const int*)objp)[i];
        }

        const float* p = pred + (size_t)i * 30;   // byte offset 120*i, 8B aligned
        float2 a0 = *(const float2*)(p + 0);
        float2 a1 = *(const float2*)(p + 2);
        float2 a2 = *(const float2*)(p + 4);
        float2 a3 = *(const float2*)(p + 6);
        float2 a4 = *(const float2*)(p + 8);
        // b1 = (a0.x, a0.y, a1.x, a1.y | conf a2.x)
        // b2 = (a2.y, a3.x, a3.y, a4.x | conf a4.y)

        if (obj > 0.5f) {
            v_nobj = 1.0f;

            float4 tb = ((const float4*)tbox)[i];   // byte offset 16*i, aligned
            float tcx = tb.x * S_INV, tcy = tb.y * S_INV;
            float tx1 = tcx - 0.5f * tb.z, ty1 = tcy - 0.5f * tb.w;
            float tx2 = tcx + 0.5f * tb.z, ty2 = tcy + 0.5f * tb.w;

            float b1x = a0.x, b1y = a0.y, b1w = a1.x, b1h = a1.y, b1c = a2.x;
            float b2x = a2.y, b2y = a3.x, b2w = a3.y, b2h = a4.x, b2c = a4.y;

            float c1x = b1x * S_INV, c1y = b1y * S_INV;
            float c2x = b2x * S_INV, c2y = b2y * S_INV;

            float iou1 = iou_xyxy(c1x - 0.5f * b1w, c1y - 0.5f * b1h,
                                  c1x + 0.5f * b1w, c1y + 0.5f * b1h,
                                  tx1, ty1, tx2, ty2);
            float iou2 = iou_xyxy(c2x - 0.5f * b2w, c2y - 0.5f * b2h,
                                  c2x + 0.5f * b2w, c2y + 0.5f * b2h,
                                  tx1, ty1, tx2, ty2);

            bool take1 = (iou1 >= iou2);
            float bx = take1 ? b1x : b2x;
            float by = take1 ? b1y : b2y;
            float bw = take1 ? b1w : b2w;
            float bh = take1 ? b1h : b2h;
            float bc = take1 ? b1c : b2c;
            float biou = take1 ? iou1 : iou2;

            float dx = bx - tb.x;
            float dy = by - tb.y;
            float dw = sqrtf(bw) - sqrtf(tb.z);
            float dh = sqrtf(bh) - sqrtf(tb.w);
            v_reg = dx * dx + dy * dy + dw * dw + dh * dh;

            float dc = bc - biou;
            v_conf = dc * dc;

            // class loss: only loaded for obj cells (~30%) -> big DRAM savings
            const float2* pc = (const float2*)(p + 10);            // 8B aligned
            const float4* tc = (const float4*)(tcls + (size_t)i * 20); // 16B aligned
            float s = 0.0f;
            #pragma unroll
            for (int j = 0; j < 5; j++) {
                float4 t  = tc[j];
                float2 c0 = pc[2 * j];
                float2 c1 = pc[2 * j + 1];
                float d0 = c0.x - t.x, d1 = c0.y - t.y;
                float d2 = c1.x - t.z, d3 = c1.y - t.w;
                s += d0 * d0 + d1 * d1 + d2 * d2 + d3 * d3;
            }
            v_cls = s;
        } else {
            v_noobj = a0.x * a0.x + a0.y * a0.y + a1.x * a1.x + a1.y * a1.y
                    + a2.x * a2.x + a2.y * a2.y + a3.x * a3.x + a3.y * a3.y
                    + a4.x * a4.x + a4.y * a4.y;
        }
    }

    // warp reduce (float is fine at 32-element granularity)
    const unsigned m = 0xffffffffu;
    #pragma unroll
    for (int off = 16; off > 0; off >>= 1) {
        v_nobj  += __shfl_down_sync(m, v_nobj,  off);
        v_cls   += __shfl_down_sync(m, v_cls,   off);
        v_noobj += __shfl_down_sync(m, v_noobj, off);
        v_reg   += __shfl_down_sync(m, v_reg,   off);
        v_conf  += __shfl_down_sync(m, v_conf,  off);
    }

    __shared__ double sacc[5];
    if (threadIdx.x < 5) sacc[threadIdx.x] = 0.0;
    __syncthreads();
    if ((threadIdx.x & 31) == 0) {
        atomicAdd(&sacc[0], (double)v_nobj);
        atomicAdd(&sacc[1], (double)v_cls);
        atomicAdd(&sacc[2], (double)v_noobj);
        atomicAdd(&sacc[3], (double)v_reg);
        atomicAdd(&sacc[4], (double)v_conf);
    }
    __syncthreads();
    if (threadIdx.x < 5)
        atomicAdd(&g_acc[threadIdx.x], sacc[threadIdx.x]);
}

__global__ void finalize_kernel(float* __restrict__ out, float Nf, float total_cells) {
    double n_obj   = g_acc[0];
    double n_noobj = (double)total_cells - n_obj;
    double cls   = g_acc[1] / (double)Nf;
    double noobj = 0.5 * g_acc[2] / n_noobj;
    double reg   = 5.0 * g_acc[3] / n_obj;
    double conf  = g_acc[4] / n_obj;
    out[0] = (float)(reg + conf + noobj + cls);
    out[1] = (float)reg;
    out[2] = (float)conf;
    out[3] = (float)noobj;
    out[4] = (float)cls;
}

extern "C" void kernel_launch(void* const* d_in, const int* in_sizes, int n_in,
                              void* d_out, int out_size)
{
    const float* pred = (const float*)d_in[0];
    const float* tbox = (const float*)d_in[1];
    const float* tcls = (const float*)d_in[2];
    const void*  objp = d_in[3];

    int ncells = in_sizes[1] / 4;          // target_boxes has 4 floats/cell
    int nbatch = in_sizes[0] / (14 * 14 * 30);

    init_kernel<<<1, 32>>>();
    detect_kernel<<<128, 256>>>((const unsigned char*)objp, ncells);

    int blocks = (ncells + 255) / 256;
    yolo_kernel<<<blocks, 256>>>(pred, tbox, tcls, objp, ncells);

    finalize_kernel<<<1, 1>>>((float*)d_out, (float)nbatch, (float)ncells);
}

// round 8
// speedup vs baseline: 1.2759x; 1.2759x over previous
#include <cuda_runtime.h>
#include <math.h>

// ---------------------------------------------------------------------------
// YoloLoss, single fused kernel:
//   - per-block dtype detection of has_object_map from a 4KB prefix
//   - sparse loads: class/target data only touched for obj cells (~30%)
//   - block partials -> global double atomics -> last-block finalize
// One kernel launch per call => minimal graph-node overhead.
// ---------------------------------------------------------------------------

#define S_INV (1.0f / 14.0f)

// acc[0]=n_obj, [1]=cls, [2]=noobj, [3]=reg, [4]=conf. Zero at load; the
// finalizing block restores them to zero after use (invariant-restoring,
// deterministic across graph replays).
__device__ double g_acc[5];
__device__ unsigned int g_done;   // zero-initialized; restored to 0 by finalizer

__device__ __forceinline__ float iou_xyxy(
    float x1, float y1, float x2, float y2,
    float tx1, float ty1, float tx2, float ty2)
{
    float lx = fmaxf(x1, tx1), ly = fmaxf(y1, ty1);
    float rx = fminf(x2, tx2), ry = fminf(y2, ty2);
    float w = fmaxf(rx - lx, 0.0f), h = fmaxf(ry - ly, 0.0f);
    float inter = w * h;
    float a1 = (x2 - x1) * (y2 - y1);
    float a2 = (tx2 - tx1) * (ty2 - ty1);
    return inter / (a1 + a2 - inter);
}

__device__ __forceinline__ void process_cell(
    const float* __restrict__ pred,
    const float* __restrict__ tbox,
    const float* __restrict__ tcls,
    float obj, int i,
    float& v_nobj, float& v_cls, float& v_noobj, float& v_reg, float& v_conf)
{
    const float* p = pred + (size_t)i * 30;   // 120*i bytes, 8B aligned
    float2 a0 = *(const float2*)(p + 0);
    float2 a1 = *(const float2*)(p + 2);
    float2 a2 = *(const float2*)(p + 4);
    float2 a3 = *(const float2*)(p + 6);
    float2 a4 = *(const float2*)(p + 8);

    if (obj > 0.5f) {
        v_nobj += 1.0f;

        float4 tb = ((const float4*)tbox)[i];
        float tcx = tb.x * S_INV, tcy = tb.y * S_INV;
        float tx1 = tcx - 0.5f * tb.z, ty1 = tcy - 0.5f * tb.w;
        float tx2 = tcx + 0.5f * tb.z, ty2 = tcy + 0.5f * tb.w;

        float b1x = a0.x, b1y = a0.y, b1w = a1.x, b1h = a1.y, b1c = a2.x;
        float b2x = a2.y, b2y = a3.x, b2w = a3.y, b2h = a4.x, b2c = a4.y;

        float c1x = b1x * S_INV, c1y = b1y * S_INV;
        float c2x = b2x * S_INV, c2y = b2y * S_INV;

        float iou1 = iou_xyxy(c1x - 0.5f * b1w, c1y - 0.5f * b1h,
                              c1x + 0.5f * b1w, c1y + 0.5f * b1h,
                              tx1, ty1, tx2, ty2);
        float iou2 = iou_xyxy(c2x - 0.5f * b2w, c2y - 0.5f * b2h,
                              c2x + 0.5f * b2w, c2y + 0.5f * b2h,
                              tx1, ty1, tx2, ty2);

        bool take1 = (iou1 >= iou2);
        float bx = take1 ? b1x : b2x;
        float by = take1 ? b1y : b2y;
        float bw = take1 ? b1w : b2w;
        float bh = take1 ? b1h : b2h;
        float bc = take1 ? b1c : b2c;
        float biou = take1 ? iou1 : iou2;

        float dx = bx - tb.x;
        float dy = by - tb.y;
        float dw = sqrtf(bw) - sqrtf(tb.z);
        float dh = sqrtf(bh) - sqrtf(tb.w);
        v_reg += dx * dx + dy * dy + dw * dw + dh * dh;

        float dc = bc - biou;
        v_conf += dc * dc;

        // class loss: touched only for obj cells -> ~45 MB DRAM saved
        const float2* pc = (const float2*)(p + 10);
        const float4* tc = (const float4*)(tcls + (size_t)i * 20);
        float s = 0.0f;
        #pragma unroll
        for (int j = 0; j < 5; j++) {
            float4 t  = tc[j];
            float2 c0 = pc[2 * j];
            float2 c1 = pc[2 * j + 1];
            float d0 = c0.x - t.x, d1 = c0.y - t.y;
            float d2 = c1.x - t.z, d3 = c1.y - t.w;
            s += d0 * d0 + d1 * d1 + d2 * d2 + d3 * d3;
        }
        v_cls += s;
    } else {
        v_noobj += a0.x * a0.x + a0.y * a0.y + a1.x * a1.x + a1.y * a1.y
                 + a2.x * a2.x + a2.y * a2.y + a3.x * a3.x + a3.y * a3.y
                 + a4.x * a4.x + a4.y * a4.y;
    }
}

// 2 cells per thread: grid = ceil(ncells / 512) blocks of 256 threads
__global__ void __launch_bounds__(256)
yolo_fused(const float* __restrict__ pred,
           const float* __restrict__ tbox,
           const float* __restrict__ tcls,
           const void*  __restrict__ objp,
           float* __restrict__ out,
           int ncells, float Nf, int nblocks)
{
    int tid = threadIdx.x;

    // ---- dtype detection from 4KB prefix (one uint4 per thread) ----------
    //   float32 1.0f = 00 00 80 3F : some byte > 1           -> gt1
    //   uint8   0/1  : nonzero byte at offset %4 != 0        -> off4
    //   int32   0/1  : nonzero only at byte offset %4 == 0   -> neither
    uint4 w = ((const uint4*)objp)[tid];
    unsigned v_all = w.x | w.y | w.z | w.w;
    int l_gt1  = (v_all & 0xFEFEFEFEu) != 0;   // any byte with bits above 1
    int l_off4 = (v_all & 0xFFFFFF00u) != 0;   // any nonzero byte at pos 1..3
    int gt1  = __syncthreads_or(l_gt1);
    int off4 = __syncthreads_or(l_off4);
    int dt = gt1 ? 2 : (off4 ? 1 : 0);         // 2=f32, 1=u8, 0=i32

    // ---- main loop --------------------------------------------------------
    float v_nobj = 0.0f, v_cls = 0.0f, v_noobj = 0.0f, v_reg = 0.0f, v_conf = 0.0f;

    int base = blockIdx.x * 512 + tid;
    #pragma unroll
    for (int k = 0; k < 2; k++) {
        int i = base + k * 256;
        if (i < ncells) {
            float obj;
            if (dt == 2)      obj = ((const float*)objp)[i];
            else if (dt == 1) obj = (float)((const unsigned char*)objp)[i];
            else              obj = (float)((const int*)objp)[i];
            process_cell(pred, tbox, tcls, obj, i,
                         v_nobj, v_cls, v_noobj, v_reg, v_conf);
        }
    }

    // ---- block reduction ---------------------------------------------------
    const unsigned m = 0xffffffffu;
    #pragma unroll
    for (int off = 16; off > 0; off >>= 1) {
        v_nobj  += __shfl_down_sync(m, v_nobj,  off);
        v_cls   += __shfl_down_sync(m, v_cls,   off);
        v_noobj += __shfl_down_sync(m, v_noobj, off);
        v_reg   += __shfl_down_sync(m, v_reg,   off);
        v_conf  += __shfl_down_sync(m, v_conf,  off);
    }

    __shared__ double sacc[5];
    if (tid < 5) sacc[tid] = 0.0;
    __syncthreads();
    if ((tid & 31) == 0) {
        atomicAdd(&sacc[0], (double)v_nobj);
        atomicAdd(&sacc[1], (double)v_cls);
        atomicAdd(&sacc[2], (double)v_noobj);
        atomicAdd(&sacc[3], (double)v_reg);
        atomicAdd(&sacc[4], (double)v_conf);
    }
    __syncthreads();
    if (tid < 5)
        atomicAdd(&g_acc[tid], sacc[tid]);

    // ---- last-block finalize ----------------------------------------------
    __threadfence();                           // release our g_acc adds
    __shared__ unsigned int ticket;
    if (tid == 0) ticket = atomicAdd(&g_done, 1u);
    __syncthreads();
    if (ticket == (unsigned)(nblocks - 1) && tid == 0) {
        __threadfence();                       // acquire all g_acc adds
        double n_obj   = g_acc[0];
        double n_noobj = (double)ncells - n_obj;
        double cls   = g_acc[1] / (double)Nf;
        double noobj = 0.5 * g_acc[2] / n_noobj;
        double reg   = 5.0 * g_acc[3] / n_obj;
        double conf  = g_acc[4] / n_obj;
        out[0] = (float)(reg + conf + noobj + cls);
        out[1] = (float)reg;
        out[2] = (float)conf;
        out[3] = (float)noobj;
        out[4] = (float)cls;
        // restore invariant for the next (graph-replayed) call
        g_acc[0] = 0.0; g_acc[1] = 0.0; g_acc[2] = 0.0;
        g_acc[3] = 0.0; g_acc[4] = 0.0;
        g_done = 0u;
    }
}

extern "C" void kernel_launch(void* const* d_in, const int* in_sizes, int n_in,
                              void* d_out, int out_size)
{
    const float* pred = (const float*)d_in[0];
    const float* tbox = (const float*)d_in[1];
    const float* tcls = (const float*)d_in[2];
    const void*  objp = d_in[3];

    int ncells = in_sizes[1] / 4;              // target_boxes: 4 floats/cell
    int nbatch = in_sizes[0] / (14 * 14 * 30);
    int nblocks = (ncells + 511) / 512;        // 1568 for the reference shape

    yolo_fused<<<nblocks, 256>>>(pred, tbox, tcls, objp,
                                 (float*)d_out, ncells, (float)nbatch, nblocks);
}